// round 5
// baseline (speedup 1.0000x reference)
#include <cuda_runtime.h>
#include <math.h>

#define NN 10000
#define NJP 10240
#define NV 2500            // NN/4 (int4 / nibble granularity)
#define NG 2500            // row groups of 4
#define OUTF 64
#define SMAX 10016
#define LN001 (-4.605170185988091f)
#define EPS_SL 0.02f

// ---- static scratch ----
__device__ float    g_Wh[NN * OUTF];
__device__ float    g_esrc[NN];
__device__ int      g_Emax;
__device__ float2   g_edst[NN];       // {ed, -} stash from gemm
__device__ float4   g_jd[NJP];        // {ed, bp, bn, hub*0.01}
__device__ float2   g_kab[NJP];       // {kA=ed-lnh, kB=ed-5lnh}
__device__ float    g_tp[NJP];        // ed
__device__ float    g_tbp[NJP];       // exp(ed-E)
__device__ float    g_tbn[NJP];       // exp(0.2(ed-E))
__device__ unsigned g_nib4[(size_t)NG * NV];  // [group][v], byte r = nibble row 4g+r
__device__ float4   g_rowp[NN];       // {dA, dB, rpy, rpz}
__device__ float    g_rowns[NN];      // -esrc
__device__ int      g_cnt[NN];
__device__ float2   g_sv[(size_t)NN * SMAX];  // {w, j_as_bits}

__device__ __forceinline__ int fkey(float x) {
    int ix = __float_as_int(x);
    return ix >= 0 ? ix : (ix ^ 0x7fffffff);
}
__device__ __forceinline__ float funkey(int k) {
    return __int_as_float(k >= 0 ? k : (k ^ 0x7fffffff));
}

// ---------------------------------------------------------------------------
// K1: Wh = h @ W (64x64 tile) + fused edge dots + Emax
// ---------------------------------------------------------------------------
__global__ void k_gemm(const float* __restrict__ h, const float* __restrict__ W,
                       const float* __restrict__ a_src, const float* __restrict__ a_dst) {
    __shared__ float h_s[64][33];
    __shared__ float W_s[32][64];
    __shared__ int bmax;
    int tid = threadIdx.x;
    if (tid == 0) bmax = 0x80000000;
    int tx = tid & 15, ty = tid >> 4;
    int gr0 = blockIdx.x * 64;
    float acc[4][4];
#pragma unroll
    for (int i = 0; i < 4; i++)
#pragma unroll
        for (int j = 0; j < 4; j++) acc[i][j] = 0.f;

    for (int k0 = 0; k0 < 512; k0 += 32) {
        __syncthreads();
#pragma unroll
        for (int it = 0; it < 2; it++) {
            int idx = it * 256 + tid;
            int row = idx >> 3, q = idx & 7;
            float4 h4 = make_float4(0.f, 0.f, 0.f, 0.f);
            if (gr0 + row < NN)
                h4 = *reinterpret_cast<const float4*>(h + (size_t)(gr0 + row) * 512 + k0 + q * 4);
            h_s[row][q * 4 + 0] = h4.x; h_s[row][q * 4 + 1] = h4.y;
            h_s[row][q * 4 + 2] = h4.z; h_s[row][q * 4 + 3] = h4.w;
        }
#pragma unroll
        for (int it = 0; it < 2; it++) {
            int idx = it * 256 + tid;
            int kk = idx >> 4, c4 = (idx & 15) * 4;
            float4 w4 = *reinterpret_cast<const float4*>(W + (size_t)(k0 + kk) * OUTF + c4);
            *reinterpret_cast<float4*>(&W_s[kk][c4]) = w4;
        }
        __syncthreads();
#pragma unroll
        for (int kk = 0; kk < 32; kk++) {
            float4 wv = *reinterpret_cast<const float4*>(&W_s[kk][tx * 4]);
            float hv0 = h_s[ty * 4 + 0][kk];
            float hv1 = h_s[ty * 4 + 1][kk];
            float hv2 = h_s[ty * 4 + 2][kk];
            float hv3 = h_s[ty * 4 + 3][kk];
            acc[0][0] = fmaf(hv0, wv.x, acc[0][0]); acc[0][1] = fmaf(hv0, wv.y, acc[0][1]);
            acc[0][2] = fmaf(hv0, wv.z, acc[0][2]); acc[0][3] = fmaf(hv0, wv.w, acc[0][3]);
            acc[1][0] = fmaf(hv1, wv.x, acc[1][0]); acc[1][1] = fmaf(hv1, wv.y, acc[1][1]);
            acc[1][2] = fmaf(hv1, wv.z, acc[1][2]); acc[1][3] = fmaf(hv1, wv.w, acc[1][3]);
            acc[2][0] = fmaf(hv2, wv.x, acc[2][0]); acc[2][1] = fmaf(hv2, wv.y, acc[2][1]);
            acc[2][2] = fmaf(hv2, wv.z, acc[2][2]); acc[2][3] = fmaf(hv2, wv.w, acc[2][3]);
            acc[3][0] = fmaf(hv3, wv.x, acc[3][0]); acc[3][1] = fmaf(hv3, wv.y, acc[3][1]);
            acc[3][2] = fmaf(hv3, wv.z, acc[3][2]); acc[3][3] = fmaf(hv3, wv.w, acc[3][3]);
        }
    }
    float4 as4 = *reinterpret_cast<const float4*>(a_src + tx * 4);
    float4 ad4 = *reinterpret_cast<const float4*>(a_dst + tx * 4);
#pragma unroll
    for (int i = 0; i < 4; i++) {
        int row = gr0 + ty * 4 + i;
        if (row < NN) {
            float4 o; o.x = acc[i][0]; o.y = acc[i][1]; o.z = acc[i][2]; o.w = acc[i][3];
            *reinterpret_cast<float4*>(g_Wh + (size_t)row * OUTF + tx * 4) = o;
        }
        float ps = acc[i][0] * as4.x + acc[i][1] * as4.y + acc[i][2] * as4.z + acc[i][3] * as4.w;
        float pd = acc[i][0] * ad4.x + acc[i][1] * ad4.y + acc[i][2] * ad4.z + acc[i][3] * ad4.w;
#pragma unroll
        for (int o = 8; o; o >>= 1) {
            ps += __shfl_xor_sync(0xffffffffu, ps, o);
            pd += __shfl_xor_sync(0xffffffffu, pd, o);
        }
        if (tx == 0 && row < NN) {
            g_esrc[row] = ps;
            float2 kk; kk.x = pd; kk.y = 0.f;
            g_edst[row] = kk;
            atomicMax(&bmax, fkey(pd));
        }
    }
    __syncthreads();
    if (tid == 0) atomicMax(&g_Emax, bmax);
}

// ---------------------------------------------------------------------------
// K2: per-j tables
// ---------------------------------------------------------------------------
__global__ void k_jtab(const float* __restrict__ hub) {
    int i = blockIdx.x * 256 + threadIdx.x;
    if (i >= NJP) return;
    if (i < NN) {
        float E = funkey(g_Emax);
        float ed = g_edst[i].x;
        float bp = expf(ed - E);
        float bn = expf(0.2f * (ed - E));
        float hb = hub[i];
        float lh = logf(hb);
        float4 jd; jd.x = ed; jd.y = bp; jd.z = bn; jd.w = hb * 0.01f;
        g_jd[i] = jd;
        float2 kk; kk.x = ed - lh; kk.y = ed - 5.0f * lh;
        g_kab[i] = kk;
        g_tp[i] = ed; g_tbp[i] = bp; g_tbn[i] = bn;
    } else {
        float2 kk; kk.x = -3.0e38f; kk.y = -3.0e38f;
        g_kab[i] = kk;
        g_tp[i] = 0.f; g_tbp[i] = 0.f; g_tbn[i] = 0.f;
        float4 jd; jd.x = 0.f; jd.y = 0.f; jd.z = 0.f; jd.w = 3.0e38f;
        g_jd[i] = jd;
    }
}

// ---------------------------------------------------------------------------
// K3: pure adj -> nibble stream. 8 rows/block (2 groups), minimal ALU.
// adj values are exactly {0,1}: bit = value.
// ---------------------------------------------------------------------------
__global__ void __launch_bounds__(256, 6) k_scan(const int* __restrict__ adj) {
    int t = threadIdx.x;
    int b = blockIdx.x;
    int r0 = b * 8;
    const int4* adj4 = reinterpret_cast<const int4*>(adj);
    unsigned* nr0 = g_nib4 + (size_t)(b * 2) * NV;
    unsigned* nr1 = g_nib4 + (size_t)(b * 2 + 1) * NV;

    for (int v = t; v < NV; v += 256) {
        int4 a0 = __ldcs(&adj4[(size_t)(r0 + 0) * NV + v]);
        int4 a1 = __ldcs(&adj4[(size_t)(r0 + 1) * NV + v]);
        int4 a2 = __ldcs(&adj4[(size_t)(r0 + 2) * NV + v]);
        int4 a3 = __ldcs(&adj4[(size_t)(r0 + 3) * NV + v]);
        int4 a4 = __ldcs(&adj4[(size_t)(r0 + 4) * NV + v]);
        int4 a5 = __ldcs(&adj4[(size_t)(r0 + 5) * NV + v]);
        int4 a6 = __ldcs(&adj4[(size_t)(r0 + 6) * NV + v]);
        int4 a7 = __ldcs(&adj4[(size_t)(r0 + 7) * NV + v]);
        unsigned n0 = (unsigned)(a0.x + a0.y * 2 + a0.z * 4 + a0.w * 8);
        unsigned n1 = (unsigned)(a1.x + a1.y * 2 + a1.z * 4 + a1.w * 8);
        unsigned n2 = (unsigned)(a2.x + a2.y * 2 + a2.z * 4 + a2.w * 8);
        unsigned n3 = (unsigned)(a3.x + a3.y * 2 + a3.z * 4 + a3.w * 8);
        unsigned n4 = (unsigned)(a4.x + a4.y * 2 + a4.z * 4 + a4.w * 8);
        unsigned n5 = (unsigned)(a5.x + a5.y * 2 + a5.z * 4 + a5.w * 8);
        unsigned n6 = (unsigned)(a6.x + a6.y * 2 + a6.z * 4 + a6.w * 8);
        unsigned n7 = (unsigned)(a7.x + a7.y * 2 + a7.z * 4 + a7.w * 8);
        nr0[v] = n0 | (n1 << 8) | (n2 << 16) | (n3 << 24);
        nr1[v] = n4 | (n5 << 8) | (n6 << 16) | (n7 << 24);
    }
}

// ---------------------------------------------------------------------------
// K4: Sp/Sn per row from nibbles + tables; fused row-param finalize.
// Block per 4-row group (2500 blocks), 256 threads.
// ---------------------------------------------------------------------------
__global__ void __launch_bounds__(256) k_sums() {
    int t = threadIdx.x, warp = t >> 5;
    int g = blockIdx.x;
    int r0 = g * 4;
    float ns[4], sp[4], sn[4];
#pragma unroll
    for (int r = 0; r < 4; r++) { ns[r] = -g_esrc[r0 + r]; sp[r] = 0.f; sn[r] = 0.f; }

    const unsigned* nibrow = g_nib4 + (size_t)g * NV;
    const float4* ed4p = reinterpret_cast<const float4*>(g_tp);
    const float4* bp4p = reinterpret_cast<const float4*>(g_tbp);
    const float4* bn4p = reinterpret_cast<const float4*>(g_tbn);

    for (int v = t; v < NV; v += 256) {
        unsigned nb = nibrow[v];
        float4 e4 = ed4p[v];
        float4 p4 = bp4p[v];
        float4 n4 = bn4p[v];
#pragma unroll
        for (int r = 0; r < 4; r++) {
            unsigned nr = nb >> (8 * r);
            float nsr = ns[r];
            bool o0 = nr & 1u, o1 = nr & 2u, o2 = nr & 4u, o3 = nr & 8u;
            bool q0 = e4.x > nsr, q1 = e4.y > nsr, q2 = e4.z > nsr, q3 = e4.w > nsr;
            sp[r] += ((o0 && q0) ? p4.x : 0.f) + ((o1 && q1) ? p4.y : 0.f)
                   + ((o2 && q2) ? p4.z : 0.f) + ((o3 && q3) ? p4.w : 0.f);
            sn[r] += ((o0 && !q0) ? n4.x : 0.f) + ((o1 && !q1) ? n4.y : 0.f)
                   + ((o2 && !q2) ? n4.z : 0.f) + ((o3 && !q3) ? n4.w : 0.f);
        }
    }
    __shared__ float ssp[4][8], ssn[4][8];
#pragma unroll
    for (int r = 0; r < 4; r++) {
        float b = sp[r], c = sn[r];
#pragma unroll
        for (int o = 16; o; o >>= 1) {
            b += __shfl_xor_sync(0xffffffffu, b, o);
            c += __shfl_xor_sync(0xffffffffu, c, o);
        }
        if ((t & 31) == 0) { ssp[r][warp] = b; ssn[r][warp] = c; }
    }
    __syncthreads();
    if (t < 4) {
        float Sp = ssp[t][0], Sn = ssn[t][0];
#pragma unroll
        for (int w = 1; w < 8; w++) { Sp += ssp[t][w]; Sn += ssn[t][w]; }
        int row = r0 + t;
        float es = g_esrc[row], E = funkey(g_Emax);
        float x = es + E;
        float m = x > 0.f ? x : 0.2f * x;
        float cpE = expf(x - m);
        float cnE = expf(0.2f * x - m);
        float s = cpE * Sp + cnE * Sn;
        float inv = 1.0f / s;
        float L = m + logf(s) + LN001;
        float4 rp;
        rp.x = es + EPS_SL - L;          // dA
        rp.y = es + EPS_SL - 5.0f * L;   // dB
        rp.z = cpE * inv;                // rpy
        rp.w = cnE * inv;                // rpz
        g_rowp[row] = rp;
        g_rowns[row] = -es;
    }
}

// ---------------------------------------------------------------------------
// K5: prune — candidates via max(kA+dA, kB+dB) > 0 screen; exact w refilter;
// emit (w, j) via global atomics. Block per group, 256 thr.
// ---------------------------------------------------------------------------
__global__ void __launch_bounds__(256) k_prune() {
    __shared__ float4 rp_s[4];
    __shared__ float ns_s[4];
    int t = threadIdx.x;
    int g = blockIdx.x;
    int r0 = g * 4;
    if (t < 4) { rp_s[t] = g_rowp[r0 + t]; ns_s[t] = g_rowns[r0 + t]; }
    __syncthreads();
    float dA[4], dB[4], rpy[4], rpz[4], nsr[4];
#pragma unroll
    for (int r = 0; r < 4; r++) {
        float4 rp = rp_s[r];
        dA[r] = rp.x; dB[r] = rp.y; rpy[r] = rp.z; rpz[r] = rp.w;
        nsr[r] = ns_s[r];
    }
    const unsigned* nibrow = g_nib4 + (size_t)g * NV;
    const float4* kab4 = reinterpret_cast<const float4*>(g_kab);

    for (int v = t; v < NV; v += 256) {
        unsigned nb = nibrow[v];
        if (!nb) continue;
        float4 k0 = kab4[2 * v];       // {kA0,kB0,kA1,kB1}
        float4 k1 = kab4[2 * v + 1];   // {kA2,kB2,kA3,kB3}
        unsigned mc = 0;
#pragma unroll
        for (int r = 0; r < 4; r++) {
            unsigned nr = nb >> (8 * r);
            float da = dA[r], db = dB[r];
            if ((nr & 1u) && fmaxf(k0.x + da, k0.y + db) > 0.f) mc |= 1u << (r * 4 + 0);
            if ((nr & 2u) && fmaxf(k0.z + da, k0.w + db) > 0.f) mc |= 1u << (r * 4 + 1);
            if ((nr & 4u) && fmaxf(k1.x + da, k1.y + db) > 0.f) mc |= 1u << (r * 4 + 2);
            if ((nr & 8u) && fmaxf(k1.z + da, k1.w + db) > 0.f) mc |= 1u << (r * 4 + 3);
        }
        while (mc) {
            int b = __ffs(mc) - 1; mc &= mc - 1;
            int r = b >> 2, q = b & 3;
            int j = v * 4 + q;
            float4 jd = g_jd[j];
            float p = (jd.x > nsr[r]) ? rpy[r] * jd.y : rpz[r] * jd.z;
            float wv = p - jd.w;
            if (wv > 0.f) {
                int row = r0 + r;
                int off = atomicAdd(&g_cnt[row], 1);
                g_sv[(size_t)row * SMAX + off] = make_float2(wv, __int_as_float(j));
            }
        }
    }
}

// ---------------------------------------------------------------------------
// K6: sparse SpMM + ELU. Warp per row (1250 blocks x 8 warps).
// ---------------------------------------------------------------------------
__global__ void __launch_bounds__(256) k_spmm(float* __restrict__ out) {
    int lane = threadIdx.x & 31;
    int row = blockIdx.x * 8 + (threadIdx.x >> 5);
    int n = g_cnt[row];
    const float2* sv = g_sv + (size_t)row * SMAX;
    const float2* whb = reinterpret_cast<const float2*>(g_Wh);
    float ax = 0.f, ay = 0.f, bx = 0.f, by = 0.f;
    int p = 0;
    for (; p + 1 < n; p += 2) {
        float2 s0 = __ldg(&sv[p]);
        float2 s1 = __ldg(&sv[p + 1]);
        int j0 = __float_as_int(s0.y), j1 = __float_as_int(s1.y);
        float2 a0 = whb[(size_t)j0 * 32 + lane];
        float2 a1 = whb[(size_t)j1 * 32 + lane];
        ax = fmaf(s0.x, a0.x, ax); ay = fmaf(s0.x, a0.y, ay);
        bx = fmaf(s1.x, a1.x, bx); by = fmaf(s1.x, a1.y, by);
    }
    if (p < n) {
        float2 s0 = __ldg(&sv[p]);
        int j0 = __float_as_int(s0.y);
        float2 a0 = whb[(size_t)j0 * 32 + lane];
        ax = fmaf(s0.x, a0.x, ax); ay = fmaf(s0.x, a0.y, ay);
    }
    ax += bx; ay += by;
    float2 o;
    o.x = ax > 0.f ? ax : expm1f(ax);
    o.y = ay > 0.f ? ay : expm1f(ay);
    reinterpret_cast<float2*>(out)[(size_t)row * 32 + lane] = o;
}

// ---------------------------------------------------------------------------
extern "C" void kernel_launch(void* const* d_in, const int* in_sizes, int n_in,
                              void* d_out, int out_size) {
    const float* h = nullptr; const float* W = nullptr;
    const float* a_src = nullptr; const float* a_dst = nullptr;
    const float* hub = nullptr; const int* adj = nullptr;
    int a_count = 0;
    for (int i = 0; i < n_in; i++) {
        int s = in_sizes[i];
        if (s == NN * 512)        h = (const float*)d_in[i];
        else if (s == 512 * OUTF) W = (const float*)d_in[i];
        else if (s == OUTF) { if (a_count++ == 0) a_src = (const float*)d_in[i];
                              else                a_dst = (const float*)d_in[i]; }
        else if (s == NN)         hub = (const float*)d_in[i];
        else if (s == NN * NN)    adj = (const int*)d_in[i];
    }

    // one-time side stream + events for fork/join overlap (host objects only)
    static cudaStream_t s2 = nullptr;
    static cudaEvent_t evF = nullptr, evJ = nullptr;
    static int inited = 0;
    if (!inited) {
        inited = 1;
        if (cudaStreamCreateWithFlags(&s2, cudaStreamNonBlocking) != cudaSuccess) s2 = nullptr;
        if (s2) {
            if (cudaEventCreateWithFlags(&evF, cudaEventDisableTiming) != cudaSuccess ||
                cudaEventCreateWithFlags(&evJ, cudaEventDisableTiming) != cudaSuccess) {
                s2 = nullptr;
            }
        }
    }

    void* emax_ptr = nullptr; void* cnt_ptr = nullptr;
    cudaGetSymbolAddress(&emax_ptr, g_Emax);
    cudaGetSymbolAddress(&cnt_ptr, g_cnt);
    cudaMemsetAsync(emax_ptr, 0x80, sizeof(int));
    cudaMemsetAsync(cnt_ptr, 0, NN * sizeof(int));

    if (s2) {
        cudaEventRecord(evF, 0);
        cudaStreamWaitEvent(s2, evF, 0);
        k_scan<<<1250, 256, 0, s2>>>(adj);
        k_gemm<<<157, 256>>>(h, W, a_src, a_dst);
        k_jtab<<<NJP / 256, 256>>>(hub);
        cudaEventRecord(evJ, s2);
        cudaStreamWaitEvent(0, evJ, 0);
    } else {
        k_scan<<<1250, 256>>>(adj);
        k_gemm<<<157, 256>>>(h, W, a_src, a_dst);
        k_jtab<<<NJP / 256, 256>>>(hub);
    }
    k_sums<<<NG, 256>>>();
    k_prune<<<NG, 256>>>();
    k_spmm<<<1250, 256>>>((float*)d_out);
}

// round 6
// speedup vs baseline: 1.3224x; 1.3224x over previous
#include <cuda_runtime.h>
#include <math.h>

#define NN 10000
#define NV 2500            // NN/4 (int4 / nibble granularity)
#define OUTF 64
#define SMAX 10016

// ---- static scratch ----
__device__ float    g_Wh[NN * OUTF];
__device__ float    g_esrc[NN];
__device__ float    g_ed[NN];
__device__ int      g_Emax;
__device__ float2   g_pb2[NN];        // {bp=exp(ed-E), bn=exp(0.2(ed-E))}
__device__ float    g_hT[NN];         // hub*0.01
__device__ unsigned g_nib4[(size_t)(NN / 4) * NV];  // [group of 4 rows][v]
__device__ float2   g_rw[NN];         // {rpy=1/S', rpz=rho/S'}
__device__ int      g_sj[(size_t)NN * SMAX];

__device__ __forceinline__ int fkey(float x) {
    int ix = __float_as_int(x);
    return ix >= 0 ? ix : (ix ^ 0x7fffffff);
}
__device__ __forceinline__ float funkey(int k) {
    return __int_as_float(k >= 0 ? k : (k ^ 0x7fffffff));
}

// ---------------------------------------------------------------------------
// K1: Wh = h @ W (64x64 tile) + fused edge dots + Emax
// ---------------------------------------------------------------------------
__global__ void k_gemm(const float* __restrict__ h, const float* __restrict__ W,
                       const float* __restrict__ a_src, const float* __restrict__ a_dst) {
    __shared__ float h_s[64][33];
    __shared__ float W_s[32][64];
    __shared__ int bmax;
    int tid = threadIdx.x;
    if (tid == 0) bmax = 0x80000000;
    int tx = tid & 15, ty = tid >> 4;
    int gr0 = blockIdx.x * 64;
    float acc[4][4];
#pragma unroll
    for (int i = 0; i < 4; i++)
#pragma unroll
        for (int j = 0; j < 4; j++) acc[i][j] = 0.f;

    for (int k0 = 0; k0 < 512; k0 += 32) {
        __syncthreads();
#pragma unroll
        for (int it = 0; it < 2; it++) {
            int idx = it * 256 + tid;
            int row = idx >> 3, q = idx & 7;
            float4 h4 = make_float4(0.f, 0.f, 0.f, 0.f);
            if (gr0 + row < NN)
                h4 = *reinterpret_cast<const float4*>(h + (size_t)(gr0 + row) * 512 + k0 + q * 4);
            h_s[row][q * 4 + 0] = h4.x; h_s[row][q * 4 + 1] = h4.y;
            h_s[row][q * 4 + 2] = h4.z; h_s[row][q * 4 + 3] = h4.w;
        }
#pragma unroll
        for (int it = 0; it < 2; it++) {
            int idx = it * 256 + tid;
            int kk = idx >> 4, c4 = (idx & 15) * 4;
            float4 w4 = *reinterpret_cast<const float4*>(W + (size_t)(k0 + kk) * OUTF + c4);
            *reinterpret_cast<float4*>(&W_s[kk][c4]) = w4;
        }
        __syncthreads();
#pragma unroll
        for (int kk = 0; kk < 32; kk++) {
            float4 wv = *reinterpret_cast<const float4*>(&W_s[kk][tx * 4]);
            float hv0 = h_s[ty * 4 + 0][kk];
            float hv1 = h_s[ty * 4 + 1][kk];
            float hv2 = h_s[ty * 4 + 2][kk];
            float hv3 = h_s[ty * 4 + 3][kk];
            acc[0][0] = fmaf(hv0, wv.x, acc[0][0]); acc[0][1] = fmaf(hv0, wv.y, acc[0][1]);
            acc[0][2] = fmaf(hv0, wv.z, acc[0][2]); acc[0][3] = fmaf(hv0, wv.w, acc[0][3]);
            acc[1][0] = fmaf(hv1, wv.x, acc[1][0]); acc[1][1] = fmaf(hv1, wv.y, acc[1][1]);
            acc[1][2] = fmaf(hv1, wv.z, acc[1][2]); acc[1][3] = fmaf(hv1, wv.w, acc[1][3]);
            acc[2][0] = fmaf(hv2, wv.x, acc[2][0]); acc[2][1] = fmaf(hv2, wv.y, acc[2][1]);
            acc[2][2] = fmaf(hv2, wv.z, acc[2][2]); acc[2][3] = fmaf(hv2, wv.w, acc[2][3]);
            acc[3][0] = fmaf(hv3, wv.x, acc[3][0]); acc[3][1] = fmaf(hv3, wv.y, acc[3][1]);
            acc[3][2] = fmaf(hv3, wv.z, acc[3][2]); acc[3][3] = fmaf(hv3, wv.w, acc[3][3]);
        }
    }
    float4 as4 = *reinterpret_cast<const float4*>(a_src + tx * 4);
    float4 ad4 = *reinterpret_cast<const float4*>(a_dst + tx * 4);
#pragma unroll
    for (int i = 0; i < 4; i++) {
        int row = gr0 + ty * 4 + i;
        if (row < NN) {
            float4 o; o.x = acc[i][0]; o.y = acc[i][1]; o.z = acc[i][2]; o.w = acc[i][3];
            *reinterpret_cast<float4*>(g_Wh + (size_t)row * OUTF + tx * 4) = o;
        }
        float ps = acc[i][0] * as4.x + acc[i][1] * as4.y + acc[i][2] * as4.z + acc[i][3] * as4.w;
        float pd = acc[i][0] * ad4.x + acc[i][1] * ad4.y + acc[i][2] * ad4.z + acc[i][3] * ad4.w;
#pragma unroll
        for (int o = 8; o; o >>= 1) {
            ps += __shfl_xor_sync(0xffffffffu, ps, o);
            pd += __shfl_xor_sync(0xffffffffu, pd, o);
        }
        if (tx == 0 && row < NN) {
            g_esrc[row] = ps;
            g_ed[row] = pd;
            atomicMax(&bmax, fkey(pd));
        }
    }
    __syncthreads();
    if (tid == 0) atomicMax(&g_Emax, bmax);
}

// ---------------------------------------------------------------------------
// K2: per-j tables
// ---------------------------------------------------------------------------
__global__ void k_jtab(const float* __restrict__ hub) {
    int i = blockIdx.x * 256 + threadIdx.x;
    if (i >= NN) return;
    float E = funkey(g_Emax);
    float ed = g_ed[i];
    float2 pb; pb.x = expf(ed - E); pb.y = expf(0.2f * (ed - E));
    g_pb2[i] = pb;
    g_hT[i] = hub[i] * 0.01f;
}

// ---------------------------------------------------------------------------
// K3: FUSED adj stream: nibble bitmask + softmax denominator + row params.
// 8 rows per block (1250 blocks). Per pair: FMUL+FMNMX+ISETP+pred-FADD.
// Uses exp(leaky(e)-m) = max(exp(e-m), exp(0.2e-m)); rpy=1/S', rpz=rho/S'.
// ---------------------------------------------------------------------------
__global__ void __launch_bounds__(256) k_scan(const int* __restrict__ adj) {
    __shared__ float srho[8];
    __shared__ float sred[8][8];
    int t = threadIdx.x, warp = t >> 5;
    int b = blockIdx.x;
    int r0 = b * 8;
    if (t < 8) {
        float es = g_esrc[r0 + t];
        float E = funkey(g_Emax);
        srho[t] = expf(-0.8f * (es + E));
    }
    __syncthreads();
    float rho[8], S[8];
#pragma unroll
    for (int r = 0; r < 8; r++) { rho[r] = srho[r]; S[r] = 0.f; }

    const int4* adj4 = reinterpret_cast<const int4*>(adj);
    const float4* pb4 = reinterpret_cast<const float4*>(g_pb2);
    unsigned* nr0 = g_nib4 + (size_t)(b * 2) * NV;
    unsigned* nr1 = g_nib4 + (size_t)(b * 2 + 1) * NV;

    for (int v = t; v < NV; v += 256) {
        int4 a[8];
#pragma unroll
        for (int r = 0; r < 8; r++)
            a[r] = __ldcs(&adj4[(size_t)(r0 + r) * NV + v]);
        float4 p01 = pb4[2 * v];       // {bp0,bn0,bp1,bn1}
        float4 p23 = pb4[2 * v + 1];   // {bp2,bn2,bp3,bn3}
        unsigned pk0 = 0, pk1 = 0;
#pragma unroll
        for (int r = 0; r < 8; r++) {
            float rr = rho[r];
            float t0 = fmaxf(p01.x, rr * p01.y);
            float t1 = fmaxf(p01.z, rr * p01.w);
            float t2 = fmaxf(p23.x, rr * p23.y);
            float t3 = fmaxf(p23.z, rr * p23.w);
            if (a[r].x > 0) S[r] += t0;
            if (a[r].y > 0) S[r] += t1;
            if (a[r].z > 0) S[r] += t2;
            if (a[r].w > 0) S[r] += t3;
            unsigned nib = (unsigned)(a[r].x + a[r].y * 2 + a[r].z * 4 + a[r].w * 8);
            if (r < 4) pk0 |= nib << (8 * r);
            else       pk1 |= nib << (8 * (r - 4));
        }
        nr0[v] = pk0;
        nr1[v] = pk1;
    }
#pragma unroll
    for (int r = 0; r < 8; r++) {
        float s = S[r];
#pragma unroll
        for (int o = 16; o; o >>= 1) s += __shfl_xor_sync(0xffffffffu, s, o);
        if ((t & 31) == 0) sred[r][warp] = s;
    }
    __syncthreads();
    if (t < 8) {
        float s = sred[t][0];
#pragma unroll
        for (int w = 1; w < 8; w++) s += sred[t][w];
        float inv = 1.0f / s;
        float2 rw; rw.x = inv; rw.y = srho[t] * inv;
        g_rw[r0 + t] = rw;
    }
}

// ---------------------------------------------------------------------------
// K4: FUSED prune + sparse SpMM + ELU. 8 rows per block (1250 blocks).
// Prune: exact test max(rpy*bp, rpz*bn) > hub*T; emit j only.
// SpMM: warp per row, w recomputed inline, lane covers 2 cols.
// ---------------------------------------------------------------------------
__global__ void __launch_bounds__(256) k_pruneout(float* __restrict__ out) {
    __shared__ int    scnt[8];
    __shared__ float2 srw[8];
    int t = threadIdx.x;
    int b = blockIdx.x;
    int r0 = b * 8;
    if (t < 8) { srw[t] = g_rw[r0 + t]; scnt[t] = 0; }
    __syncthreads();
    float py[8], pz[8];
#pragma unroll
    for (int r = 0; r < 8; r++) { py[r] = srw[r].x; pz[r] = srw[r].y; }

    const unsigned* nr0 = g_nib4 + (size_t)(b * 2) * NV;
    const unsigned* nr1 = g_nib4 + (size_t)(b * 2 + 1) * NV;
    const float4* pb4 = reinterpret_cast<const float4*>(g_pb2);
    const float4* hT4 = reinterpret_cast<const float4*>(g_hT);

    for (int v = t; v < NV; v += 256) {
        unsigned pk0 = nr0[v], pk1 = nr1[v];
        if (!(pk0 | pk1)) continue;
        float4 p01 = pb4[2 * v];
        float4 p23 = pb4[2 * v + 1];
        float4 ht = hT4[v];
        unsigned mc = 0;
#pragma unroll
        for (int r = 0; r < 8; r++) {
            unsigned nib = ((r < 4 ? pk0 : pk1) >> (8 * (r & 3))) & 0xFu;
            float w0 = fmaxf(py[r] * p01.x, pz[r] * p01.y) - ht.x;
            float w1 = fmaxf(py[r] * p01.z, pz[r] * p01.w) - ht.y;
            float w2 = fmaxf(py[r] * p23.x, pz[r] * p23.y) - ht.z;
            float w3 = fmaxf(py[r] * p23.z, pz[r] * p23.w) - ht.w;
            if ((nib & 1u) && w0 > 0.f) mc |= 1u << (r * 4 + 0);
            if ((nib & 2u) && w1 > 0.f) mc |= 1u << (r * 4 + 1);
            if ((nib & 4u) && w2 > 0.f) mc |= 1u << (r * 4 + 2);
            if ((nib & 8u) && w3 > 0.f) mc |= 1u << (r * 4 + 3);
        }
        while (mc) {
            int bb = __ffs(mc) - 1; mc &= mc - 1;
            int r = bb >> 2, q = bb & 3;
            int off = atomicAdd(&scnt[r], 1);
            g_sj[(size_t)(r0 + r) * SMAX + off] = v * 4 + q;
        }
    }
    __syncthreads();

    // ---- SpMM: warp w handles row r0+w ----
    int lane = t & 31, w = t >> 5;
    int row = r0 + w;
    int n = scnt[w];
    float rpy = srw[w].x, rpz = srw[w].y;
    const int* sj = g_sj + (size_t)row * SMAX;
    const float2* whb = reinterpret_cast<const float2*>(g_Wh);
    float ax = 0.f, ay = 0.f, bx = 0.f, by = 0.f;
    int p = 0;
    for (; p + 1 < n; p += 2) {
        int j0 = sj[p], j1 = sj[p + 1];
        float2 t0 = g_pb2[j0], t1 = g_pb2[j1];
        float h0 = g_hT[j0], h1 = g_hT[j1];
        float2 a0 = whb[(size_t)j0 * 32 + lane];
        float2 a1 = whb[(size_t)j1 * 32 + lane];
        float w0 = fmaxf(fmaxf(rpy * t0.x, rpz * t0.y) - h0, 0.f);
        float w1 = fmaxf(fmaxf(rpy * t1.x, rpz * t1.y) - h1, 0.f);
        ax = fmaf(w0, a0.x, ax); ay = fmaf(w0, a0.y, ay);
        bx = fmaf(w1, a1.x, bx); by = fmaf(w1, a1.y, by);
    }
    if (p < n) {
        int j0 = sj[p];
        float2 t0 = g_pb2[j0];
        float h0 = g_hT[j0];
        float2 a0 = whb[(size_t)j0 * 32 + lane];
        float w0 = fmaxf(fmaxf(rpy * t0.x, rpz * t0.y) - h0, 0.f);
        ax = fmaf(w0, a0.x, ax); ay = fmaf(w0, a0.y, ay);
    }
    ax += bx; ay += by;
    float2 o;
    o.x = ax > 0.f ? ax : expm1f(ax);
    o.y = ay > 0.f ? ay : expm1f(ay);
    reinterpret_cast<float2*>(out)[(size_t)row * 32 + lane] = o;
}

// ---------------------------------------------------------------------------
extern "C" void kernel_launch(void* const* d_in, const int* in_sizes, int n_in,
                              void* d_out, int out_size) {
    const float* h = nullptr; const float* W = nullptr;
    const float* a_src = nullptr; const float* a_dst = nullptr;
    const float* hub = nullptr; const int* adj = nullptr;
    int a_count = 0;
    for (int i = 0; i < n_in; i++) {
        int s = in_sizes[i];
        if (s == NN * 512)        h = (const float*)d_in[i];
        else if (s == 512 * OUTF) W = (const float*)d_in[i];
        else if (s == OUTF) { if (a_count++ == 0) a_src = (const float*)d_in[i];
                              else                a_dst = (const float*)d_in[i]; }
        else if (s == NN)         hub = (const float*)d_in[i];
        else if (s == NN * NN)    adj = (const int*)d_in[i];
    }

    void* emax_ptr = nullptr;
    cudaGetSymbolAddress(&emax_ptr, g_Emax);
    cudaMemsetAsync(emax_ptr, 0x80, sizeof(int));

    k_gemm<<<157, 256>>>(h, W, a_src, a_dst);
    k_jtab<<<(NN + 255) / 256, 256>>>(hub);
    k_scan<<<1250, 256>>>(adj);
    k_pruneout<<<1250, 256>>>((float*)d_out);
}